// round 2
// baseline (speedup 1.0000x reference)
#include <cuda_runtime.h>
#include <cuda_bf16.h>
#include <math.h>

// Problem constants
#define NN 20000
#define EE 160000
#define DD 768
#define HH 256
#define CC 10
#define NF 513          // 2H+1
#define EPW 1026        // 2*(2H+1)

// -------- scratch (static device allocations are allowed) --------
__device__ float g_buf_h[NN * HH];     // GEMM output before aggregation
__device__ float g_buf_s[NN];          // layer-3 scalar pre-agg
__device__ float g_dinv[NN];
__device__ int   g_cnt[NN];            // in-degree (without self loop)
__device__ int   g_cursor[NN];
__device__ int   g_rowptr[NN + 1];
__device__ int   g_csr_src[EE];

// ----------------- small kernels -----------------
__global__ void k_zero2(int* a, int* b, int n) {
    int i = blockIdx.x * blockDim.x + threadIdx.x;
    if (i < n) { a[i] = 0; b[i] = 0; }
}

__global__ void k_count(const int* __restrict__ dst, int* cnt, int e) {
    int i = blockIdx.x * blockDim.x + threadIdx.x;
    if (i < e) atomicAdd(&cnt[dst[i]], 1);
}

// single-block prefix scan: rowptr[i+1] = sum_{j<=i} cnt[j]
__global__ void k_scan(const int* __restrict__ cnt, int* rowptr, int n) {
    __shared__ int wsum[32];
    __shared__ int s_carry;
    int lane = threadIdx.x & 31, wid = threadIdx.x >> 5;
    if (threadIdx.x == 0) { rowptr[0] = 0; s_carry = 0; }
    __syncthreads();
    for (int base = 0; base < n; base += 1024) {
        int i = base + threadIdx.x;
        int v = (i < n) ? cnt[i] : 0;
        int x = v;
        #pragma unroll
        for (int off = 1; off < 32; off <<= 1) {
            int t = __shfl_up_sync(0xffffffffu, x, off);
            if (lane >= off) x += t;
        }
        if (lane == 31) wsum[wid] = x;
        __syncthreads();
        if (wid == 0) {
            int w = wsum[lane];
            #pragma unroll
            for (int off = 1; off < 32; off <<= 1) {
                int t = __shfl_up_sync(0xffffffffu, w, off);
                if (lane >= off) w += t;
            }
            wsum[lane] = w;
        }
        __syncthreads();
        int carry_now = s_carry;
        int excl_w = (wid > 0) ? wsum[wid - 1] : 0;
        int incl = x + excl_w + carry_now;
        if (i < n) rowptr[i + 1] = incl;
        __syncthreads();
        if (threadIdx.x == 0) s_carry = carry_now + wsum[31];
        __syncthreads();
    }
}

__global__ void k_dinv(const int* __restrict__ cnt, float* dinv, int n) {
    int i = blockIdx.x * blockDim.x + threadIdx.x;
    if (i < n) dinv[i] = rsqrtf((float)(cnt[i] + 1));  // +1 self loop
}

__global__ void k_fill(const int* __restrict__ src, const int* __restrict__ dst,
                       const int* __restrict__ rowptr, int* cursor, int* csr_src, int e) {
    int i = blockIdx.x * blockDim.x + threadIdx.x;
    if (i < e) {
        int d = dst[i];
        int p = atomicAdd(&cursor[d], 1);
        csr_src[rowptr[d] + p] = src[i];
    }
}

// ----------------- SIMT fp32 GEMM: C = A(MxK, lda) * B(KxN, ldb) -----------------
// BM=64, BN=64, BK=16, 256 threads, 4x4 per thread
__global__ void k_gemm(const float* __restrict__ A, int lda,
                       const float* __restrict__ B, int ldb,
                       float* __restrict__ C, int ldc,
                       int M, int N, int K) {
    __shared__ float As[16][68];   // [k][m], padded (68*4B keeps 16B alignment)
    __shared__ float Bs[16][64];   // [k][n]
    const int tid = threadIdx.x;
    const int tx = tid & 15, ty = tid >> 4;
    const int row0 = blockIdx.y * 64;
    const int col0 = blockIdx.x * 64;

    float acc[4][4] = {};

    for (int k0 = 0; k0 < K; k0 += 16) {
        // load A tile transposed: As[kk][r]
        #pragma unroll
        for (int idx = tid; idx < 64 * 16; idx += 256) {
            int r = idx >> 4, kk = idx & 15;
            int gr = row0 + r;
            As[kk][r] = (gr < M) ? A[(size_t)gr * lda + k0 + kk] : 0.0f;
        }
        // load B tile: Bs[kk][c]
        #pragma unroll
        for (int idx = tid; idx < 16 * 64; idx += 256) {
            int kk = idx >> 6, c = idx & 63;
            Bs[kk][c] = B[(size_t)(k0 + kk) * ldb + col0 + c];
        }
        __syncthreads();
        #pragma unroll
        for (int kk = 0; kk < 16; ++kk) {
            float4 a = *reinterpret_cast<const float4*>(&As[kk][ty * 4]);
            float4 b = *reinterpret_cast<const float4*>(&Bs[kk][tx * 4]);
            float av[4] = {a.x, a.y, a.z, a.w};
            float bv[4] = {b.x, b.y, b.z, b.w};
            #pragma unroll
            for (int i = 0; i < 4; ++i)
                #pragma unroll
                for (int j = 0; j < 4; ++j)
                    acc[i][j] = fmaf(av[i], bv[j], acc[i][j]);
        }
        __syncthreads();
    }

    #pragma unroll
    for (int i = 0; i < 4; ++i) {
        int gr = row0 + ty * 4 + i;
        if (gr < M) {
            #pragma unroll
            for (int j = 0; j < 4; ++j)
                C[(size_t)gr * ldc + col0 + tx * 4 + j] = acc[i][j];
        }
    }
}

// ----------------- aggregation + tanh (one block per node, H threads) -----------------
// out[v*strideO + col] = tanh(dinv[v] * (sum_{src in-nbrs} h[src]*dinv[src] + h[v]*dinv[v]) + b[col])
__global__ void k_agg(const float* __restrict__ h, int strideH,
                      float* __restrict__ out, int strideO,
                      const int* __restrict__ rowptr, const int* __restrict__ csr_src,
                      const float* __restrict__ dinv, const float* __restrict__ bias) {
    int v = blockIdx.x;
    int col = threadIdx.x;
    float dv = dinv[v];
    float acc = h[(size_t)v * strideH + col] * dv;
    int e0 = rowptr[v], e1 = rowptr[v + 1];
    for (int e = e0; e < e1; ++e) {
        int s = csr_src[e];
        acc = fmaf(h[(size_t)s * strideH + col], dinv[s], acc);
    }
    out[(size_t)v * strideO + col] = tanhf(acc * dv + bias[col]);
}

// layer-3 projection: s[v] = dot(h2[v], W2)  (warp per node)
__global__ void k_dot_w2(const float* __restrict__ nf, const float* __restrict__ W2,
                         float* __restrict__ s, int n) {
    int gwarp = (blockIdx.x * blockDim.x + threadIdx.x) >> 5;
    int lane = threadIdx.x & 31;
    if (gwarp >= n) return;
    const float* row = nf + (size_t)gwarp * NF + HH;  // h2 lives at cols [256,512)
    float acc = 0.f;
    #pragma unroll
    for (int j = lane; j < HH; j += 32) acc = fmaf(row[j], W2[j], acc);
    #pragma unroll
    for (int off = 16; off; off >>= 1) acc += __shfl_xor_sync(0xffffffffu, acc, off);
    if (lane == 0) s[gwarp] = acc;
}

// scalar aggregation for layer 3 (thread per node), writes node_features col 512
__global__ void k_agg_scalar(const float* __restrict__ s, float* __restrict__ nf,
                             const int* __restrict__ rowptr, const int* __restrict__ csr_src,
                             const float* __restrict__ dinv, const float* __restrict__ b2, int n) {
    int v = blockIdx.x * blockDim.x + threadIdx.x;
    if (v >= n) return;
    float dv = dinv[v];
    float acc = s[v] * dv;
    int e1 = rowptr[v + 1];
    for (int e = rowptr[v]; e < e1; ++e) {
        int src = csr_src[e];
        acc = fmaf(s[src], dinv[src], acc);
    }
    nf[(size_t)v * NF + (NF - 1)] = tanhf(acc * dv + b2[0]);
}

// logits: warp per node, 10 outputs over a 513-length row
__global__ void k_logits(const float* __restrict__ nf, const float* __restrict__ Wc,
                         const float* __restrict__ bc, float* __restrict__ out, int n) {
    int gwarp = (blockIdx.x * blockDim.x + threadIdx.x) >> 5;
    int lane = threadIdx.x & 31;
    if (gwarp >= n) return;
    const float* row = nf + (size_t)gwarp * NF;
    float acc[CC] = {};
    for (int j = lane; j < NF; j += 32) {
        float v = row[j];
        const float* w = Wc + (size_t)j * CC;
        #pragma unroll
        for (int c = 0; c < CC; ++c) acc[c] = fmaf(v, w[c], acc[c]);
    }
    #pragma unroll
    for (int c = 0; c < CC; ++c)
        #pragma unroll
        for (int off = 16; off; off >>= 1) acc[c] += __shfl_xor_sync(0xffffffffu, acc[c], off);
    if (lane == 0) {
        #pragma unroll
        for (int c = 0; c < CC; ++c) out[(size_t)gwarp * CC + c] = acc[c] + bc[c];
    }
}

// edge pair features: block per edge, copy 2x513 floats
__global__ void k_edge_pairs(const float* __restrict__ nf,
                             const int* __restrict__ src, const int* __restrict__ dst,
                             float* __restrict__ ep, int e) {
    int eid = blockIdx.x;
    if (eid >= e) return;
    const float* rs = nf + (size_t)src[eid] * NF;
    const float* rt = nf + (size_t)dst[eid] * NF;
    float* o = ep + (size_t)eid * EPW;
    for (int j = threadIdx.x; j < NF; j += blockDim.x) {
        o[j]      = rs[j];
        o[NF + j] = rt[j];
    }
}

// ----------------- launch -----------------
extern "C" void kernel_launch(void* const* d_in, const int* in_sizes, int n_in,
                              void* d_out, int out_size) {
    const float* x    = (const float*)d_in[0];
    const int*   ei   = (const int*)d_in[1];
    const float* W0   = (const float*)d_in[2];
    const float* b0   = (const float*)d_in[3];
    const float* W1   = (const float*)d_in[4];
    const float* b1   = (const float*)d_in[5];
    const float* W2   = (const float*)d_in[6];
    const float* b2   = (const float*)d_in[7];
    const float* Wc   = (const float*)d_in[8];
    const float* bc   = (const float*)d_in[9];

    const int n = in_sizes[0] / DD;   // 20000
    const int e = in_sizes[1] / 2;    // 160000
    const int* src = ei;
    const int* dst = ei + e;

    float* out = (float*)d_out;
    float* logits = out;                               // [n, 10]
    float* nf     = out + (size_t)n * CC;              // [n, 513]
    float* ep     = nf + (size_t)n * NF;               // [e, 1026]

    // scratch addresses
    float *buf_h, *buf_s, *dinv;
    int *cnt, *cursor, *rowptr, *csr_src;
    cudaGetSymbolAddress((void**)&buf_h, g_buf_h);
    cudaGetSymbolAddress((void**)&buf_s, g_buf_s);
    cudaGetSymbolAddress((void**)&dinv, g_dinv);
    cudaGetSymbolAddress((void**)&cnt, g_cnt);
    cudaGetSymbolAddress((void**)&cursor, g_cursor);
    cudaGetSymbolAddress((void**)&rowptr, g_rowptr);
    cudaGetSymbolAddress((void**)&csr_src, g_csr_src);

    const int TB = 256;
    // degree + CSR build
    k_zero2<<<(n + TB - 1) / TB, TB>>>(cnt, cursor, n);
    k_count<<<(e + TB - 1) / TB, TB>>>(dst, cnt, e);
    k_scan<<<1, 1024>>>(cnt, rowptr, n);
    k_dinv<<<(n + TB - 1) / TB, TB>>>(cnt, dinv, n);
    k_fill<<<(e + TB - 1) / TB, TB>>>(src, dst, rowptr, cursor, csr_src, e);

    dim3 g1(HH / 64, (n + 63) / 64);
    // layer 1: GEMM (D->H), aggregate+tanh -> nf cols [0,256)
    k_gemm<<<g1, 256>>>(x, DD, W0, HH, buf_h, HH, n, HH, DD);
    k_agg<<<n, HH>>>(buf_h, HH, nf, NF, rowptr, csr_src, dinv, b0);

    // layer 2: GEMM (H->H) reading h1 from nf (stride 513), aggregate -> nf cols [256,512)
    k_gemm<<<g1, 256>>>(nf, NF, W1, HH, buf_h, HH, n, HH, HH);
    k_agg<<<n, HH>>>(buf_h, HH, nf + HH, NF, rowptr, csr_src, dinv, b1);

    // layer 3: project to scalar first, then aggregate scalars -> nf col 512
    k_dot_w2<<<(n * 32 + TB - 1) / TB, TB>>>(nf, W2, buf_s, n);
    k_agg_scalar<<<(n + TB - 1) / TB, TB>>>(buf_s, nf, rowptr, csr_src, dinv, b2, n);

    // classifier + edge pairs
    k_logits<<<(n * 32 + TB - 1) / TB, TB>>>(nf, Wc, bc, logits, n);
    k_edge_pairs<<<e, 256>>>(nf, src, dst, ep, e);
}

// round 4
// speedup vs baseline: 1.5703x; 1.5703x over previous
#include <cuda_runtime.h>
#include <cuda_bf16.h>
#include <math.h>
#include <stdint.h>

// Problem constants
#define NN 20000
#define EE 160000
#define DD 768
#define HH 256
#define CC 10
#define NF 513          // 2H+1
#define EPW 1026        // 2*(2H+1)
#define TCN 256         // GEMM N (fixed)

// -------- scratch (static device arrays are allowed) --------
__device__ float g_buf_h[NN * HH];
__device__ float g_buf_s[NN];
__device__ float g_dinv[NN];
__device__ int   g_cnt[NN];
__device__ int   g_cursor[NN];
__device__ int   g_rowptr[NN + 1];
__device__ int   g_csr_src[EE];

// ================= helpers =================
__device__ __forceinline__ uint32_t smem_u32(const void* p) {
    uint32_t a;
    asm("{ .reg .u64 t; cvta.to.shared.u64 t, %1; cvt.u32.u64 %0, t; }" : "=r"(a) : "l"(p));
    return a;
}

__device__ __forceinline__ void ldsm4(uint32_t* r, uint32_t addr) {
    asm volatile("ldmatrix.sync.aligned.m8n8.x4.shared.b16 {%0,%1,%2,%3}, [%4];"
                 : "=r"(r[0]), "=r"(r[1]), "=r"(r[2]), "=r"(r[3]) : "r"(addr));
}

__device__ __forceinline__ void mma_bf16(float* c, const uint32_t* a, const uint32_t* b) {
    asm volatile(
        "mma.sync.aligned.m16n8k16.row.col.f32.bf16.bf16.f32 "
        "{%0,%1,%2,%3}, {%4,%5,%6,%7}, {%8,%9}, {%0,%1,%2,%3};"
        : "+f"(c[0]), "+f"(c[1]), "+f"(c[2]), "+f"(c[3])
        : "r"(a[0]), "r"(a[1]), "r"(a[2]), "r"(a[3]), "r"(b[0]), "r"(b[1]));
}

// ================= tensor-core GEMM via mma.sync =================
// C[M x 256] = A[M x K](row-major, stride lda) * B[K x 256](row-major)
// bf16x3 split (hi*hi + hi*lo + lo*hi), fp32 accumulate.
// BM=128, BN=128, BK=32; 256 threads = 8 warps (2 m x 4 n); warp tile 64x32.
#define BKK 32
#define SPAD 40   // smem row stride in bf16 elems (80B: conflict-free ldsm)

__global__ void __launch_bounds__(256, 2) k_gemm_mma(
    const float* __restrict__ A, int lda,
    const float* __restrict__ B,
    float* __restrict__ C, int M, int K)
{
    __shared__ alignas(16) __nv_bfloat16 sAh[128 * SPAD];
    __shared__ alignas(16) __nv_bfloat16 sAl[128 * SPAD];
    __shared__ alignas(16) __nv_bfloat16 sBh[128 * SPAD];
    __shared__ alignas(16) __nv_bfloat16 sBl[128 * SPAD];

    const int tid = threadIdx.x;
    const int wid = tid >> 5, lane = tid & 31;
    const int row0 = blockIdx.x * 128;
    const int col0 = blockIdx.y * 128;
    const int wm = wid & 1;        // 0..1  (m position, 64 rows each)
    const int wn = wid >> 1;       // 0..3  (n position, 32 cols each)

    const uint32_t baseAh = smem_u32(sAh), baseAl = smem_u32(sAl);
    const uint32_t baseBh = smem_u32(sBh), baseBl = smem_u32(sBl);

    // ldmatrix lane->address components
    const int a_row = (lane & 7) + ((lane >> 3) & 1) * 8;   // within 16-row frag
    const int a_col = ((lane >> 4) & 1) * 8;                 // k offset within 16
    const int b_row = (lane & 7) + ((lane >> 4) & 1) * 8;   // within 16 n rows
    const int b_col = ((lane >> 3) & 1) * 8;                 // k offset within 16

    float acc[4][4][4] = {};   // [mf][nf][frag]

    for (int k0 = 0; k0 < K; k0 += BKK) {
        // ---- A tile: 128 x 32 floats -> bf16 hi/lo (coalesced along k) ----
        #pragma unroll
        for (int idx = tid; idx < 128 * BKK; idx += 256) {
            int r = idx >> 5, kk = idx & 31;
            int gr = row0 + r;
            float v = (gr < M) ? A[(size_t)gr * lda + k0 + kk] : 0.0f;
            __nv_bfloat16 hi = __float2bfloat16(v);
            __nv_bfloat16 lo = __float2bfloat16(v - __bfloat162float(hi));
            sAh[r * SPAD + kk] = hi;
            sAl[r * SPAD + kk] = lo;
        }
        // ---- B tile transposed: sB[n][kk] = B[(k0+kk)*256 + col0+n] ----
        #pragma unroll
        for (int idx = tid; idx < 128 * BKK; idx += 256) {
            int n = idx & 127, kk = idx >> 7;
            float v = B[(size_t)(k0 + kk) * TCN + col0 + n];
            __nv_bfloat16 hi = __float2bfloat16(v);
            __nv_bfloat16 lo = __float2bfloat16(v - __bfloat162float(hi));
            sBh[n * SPAD + kk] = hi;
            sBl[n * SPAD + kk] = lo;
        }
        __syncthreads();

        #pragma unroll
        for (int ks = 0; ks < 2; ++ks) {
            const int kc = ks * 16;
            uint32_t ah[4][4], al[4][4], bh[4][2], bl[4][2];

            // A hi frags (4 x m16)
            #pragma unroll
            for (int mf = 0; mf < 4; ++mf) {
                uint32_t off = (uint32_t)((wm * 64 + mf * 16 + a_row) * SPAD + kc + a_col) * 2;
                ldsm4(ah[mf], baseAh + off);
            }
            // B hi frags (2 x ldsm.x4 -> 4 n-frags)
            #pragma unroll
            for (int np = 0; np < 2; ++np) {
                uint32_t off = (uint32_t)((wn * 32 + np * 16 + b_row) * SPAD + kc + b_col) * 2;
                uint32_t t[4];
                ldsm4(t, baseBh + off);
                bh[np * 2][0] = t[0]; bh[np * 2][1] = t[1];
                bh[np * 2 + 1][0] = t[2]; bh[np * 2 + 1][1] = t[3];
            }
            // hi*hi
            #pragma unroll
            for (int mf = 0; mf < 4; ++mf)
                #pragma unroll
                for (int nf = 0; nf < 4; ++nf)
                    mma_bf16(acc[mf][nf], ah[mf], bh[nf]);
            // B lo frags, hi*lo
            #pragma unroll
            for (int np = 0; np < 2; ++np) {
                uint32_t off = (uint32_t)((wn * 32 + np * 16 + b_row) * SPAD + kc + b_col) * 2;
                uint32_t t[4];
                ldsm4(t, baseBl + off);
                bl[np * 2][0] = t[0]; bl[np * 2][1] = t[1];
                bl[np * 2 + 1][0] = t[2]; bl[np * 2 + 1][1] = t[3];
            }
            #pragma unroll
            for (int mf = 0; mf < 4; ++mf)
                #pragma unroll
                for (int nf = 0; nf < 4; ++nf)
                    mma_bf16(acc[mf][nf], ah[mf], bl[nf]);
            // A lo frags, lo*hi
            #pragma unroll
            for (int mf = 0; mf < 4; ++mf) {
                uint32_t off = (uint32_t)((wm * 64 + mf * 16 + a_row) * SPAD + kc + a_col) * 2;
                ldsm4(al[mf], baseAl + off);
            }
            #pragma unroll
            for (int mf = 0; mf < 4; ++mf)
                #pragma unroll
                for (int nf = 0; nf < 4; ++nf)
                    mma_bf16(acc[mf][nf], al[mf], bh[nf]);
        }
        __syncthreads();
    }

    // ---- epilogue: c frag layout: rows (lane>>2), (lane>>2)+8; cols (lane&3)*2 ----
    const int gq = lane >> 2, rq = lane & 3;
    #pragma unroll
    for (int mf = 0; mf < 4; ++mf) {
        int gr0 = row0 + wm * 64 + mf * 16 + gq;
        int gr1 = gr0 + 8;
        #pragma unroll
        for (int nf = 0; nf < 4; ++nf) {
            int gc = col0 + wn * 32 + nf * 8 + rq * 2;
            if (gr0 < M) {
                C[(size_t)gr0 * TCN + gc]     = acc[mf][nf][0];
                C[(size_t)gr0 * TCN + gc + 1] = acc[mf][nf][1];
            }
            if (gr1 < M) {
                C[(size_t)gr1 * TCN + gc]     = acc[mf][nf][2];
                C[(size_t)gr1 * TCN + gc + 1] = acc[mf][nf][3];
            }
        }
    }
}

// ================= small kernels =================
__global__ void k_zero2(int* a, int* b, int n) {
    int i = blockIdx.x * blockDim.x + threadIdx.x;
    if (i < n) { a[i] = 0; b[i] = 0; }
}

__global__ void k_count(const int* __restrict__ dst, int* cnt, int e) {
    int i = blockIdx.x * blockDim.x + threadIdx.x;
    if (i < e) atomicAdd(&cnt[dst[i]], 1);
}

__global__ void k_scan(const int* __restrict__ cnt, int* rowptr, int n) {
    __shared__ int wsum[32];
    __shared__ int s_carry;
    int lane = threadIdx.x & 31, wid = threadIdx.x >> 5;
    if (threadIdx.x == 0) { rowptr[0] = 0; s_carry = 0; }
    __syncthreads();
    for (int base = 0; base < n; base += 1024) {
        int i = base + threadIdx.x;
        int v = (i < n) ? cnt[i] : 0;
        int x = v;
        #pragma unroll
        for (int off = 1; off < 32; off <<= 1) {
            int t = __shfl_up_sync(0xffffffffu, x, off);
            if (lane >= off) x += t;
        }
        if (lane == 31) wsum[wid] = x;
        __syncthreads();
        if (wid == 0) {
            int w = wsum[lane];
            #pragma unroll
            for (int off = 1; off < 32; off <<= 1) {
                int t = __shfl_up_sync(0xffffffffu, w, off);
                if (lane >= off) w += t;
            }
            wsum[lane] = w;
        }
        __syncthreads();
        int carry_now = s_carry;
        int excl_w = (wid > 0) ? wsum[wid - 1] : 0;
        int incl = x + excl_w + carry_now;
        if (i < n) rowptr[i + 1] = incl;
        __syncthreads();
        if (threadIdx.x == 0) s_carry = carry_now + wsum[31];
        __syncthreads();
    }
}

__global__ void k_dinv(const int* __restrict__ cnt, float* dinv, int n) {
    int i = blockIdx.x * blockDim.x + threadIdx.x;
    if (i < n) dinv[i] = rsqrtf((float)(cnt[i] + 1));
}

__global__ void k_fill(const int* __restrict__ src, const int* __restrict__ dst,
                       const int* __restrict__ rowptr, int* cursor, int* csr_src, int e) {
    int i = blockIdx.x * blockDim.x + threadIdx.x;
    if (i < e) {
        int d = dst[i];
        int p = atomicAdd(&cursor[d], 1);
        csr_src[rowptr[d] + p] = src[i];
    }
}

__global__ void k_agg(const float* __restrict__ h, int strideH,
                      float* __restrict__ out, int strideO,
                      const int* __restrict__ rowptr, const int* __restrict__ csr_src,
                      const float* __restrict__ dinv, const float* __restrict__ bias) {
    int v = blockIdx.x;
    int col = threadIdx.x;
    float dv = dinv[v];
    float acc = h[(size_t)v * strideH + col] * dv;
    int e0 = rowptr[v], e1 = rowptr[v + 1];
    for (int e = e0; e < e1; ++e) {
        int s = csr_src[e];
        acc = fmaf(h[(size_t)s * strideH + col], dinv[s], acc);
    }
    out[(size_t)v * strideO + col] = tanhf(acc * dv + bias[col]);
}

__global__ void k_dot_w2(const float* __restrict__ nf, const float* __restrict__ W2,
                         float* __restrict__ s, int n) {
    int gwarp = (blockIdx.x * blockDim.x + threadIdx.x) >> 5;
    int lane = threadIdx.x & 31;
    if (gwarp >= n) return;
    const float* row = nf + (size_t)gwarp * NF + HH;
    float acc = 0.f;
    #pragma unroll
    for (int j = lane; j < HH; j += 32) acc = fmaf(row[j], W2[j], acc);
    #pragma unroll
    for (int off = 16; off; off >>= 1) acc += __shfl_xor_sync(0xffffffffu, acc, off);
    if (lane == 0) s[gwarp] = acc;
}

__global__ void k_agg_scalar(const float* __restrict__ s, float* __restrict__ nf,
                             const int* __restrict__ rowptr, const int* __restrict__ csr_src,
                             const float* __restrict__ dinv, const float* __restrict__ b2, int n) {
    int v = blockIdx.x * blockDim.x + threadIdx.x;
    if (v >= n) return;
    float dv = dinv[v];
    float acc = s[v] * dv;
    int e1 = rowptr[v + 1];
    for (int e = rowptr[v]; e < e1; ++e) {
        int src = csr_src[e];
        acc = fmaf(s[src], dinv[src], acc);
    }
    nf[(size_t)v * NF + (NF - 1)] = tanhf(acc * dv + b2[0]);
}

__global__ void k_logits(const float* __restrict__ nf, const float* __restrict__ Wc,
                         const float* __restrict__ bc, float* __restrict__ out, int n) {
    int gwarp = (blockIdx.x * blockDim.x + threadIdx.x) >> 5;
    int lane = threadIdx.x & 31;
    if (gwarp >= n) return;
    const float* row = nf + (size_t)gwarp * NF;
    float acc[CC] = {};
    for (int j = lane; j < NF; j += 32) {
        float v = row[j];
        const float* w = Wc + (size_t)j * CC;
        #pragma unroll
        for (int c = 0; c < CC; ++c) acc[c] = fmaf(v, w[c], acc[c]);
    }
    #pragma unroll
    for (int c = 0; c < CC; ++c)
        #pragma unroll
        for (int off = 16; off; off >>= 1) acc[c] += __shfl_xor_sync(0xffffffffu, acc[c], off);
    if (lane == 0) {
        #pragma unroll
        for (int c = 0; c < CC; ++c) out[(size_t)gwarp * CC + c] = acc[c] + bc[c];
    }
}

__global__ void k_edge_pairs(const float* __restrict__ nf,
                             const int* __restrict__ src, const int* __restrict__ dst,
                             float* __restrict__ ep, int e) {
    int eid = blockIdx.x;
    if (eid >= e) return;
    const float* rs = nf + (size_t)src[eid] * NF;
    const float* rt = nf + (size_t)dst[eid] * NF;
    float* o = ep + (size_t)eid * EPW;
    for (int j = threadIdx.x; j < NF; j += blockDim.x) {
        o[j]      = rs[j];
        o[NF + j] = rt[j];
    }
}

// ================= launch =================
extern "C" void kernel_launch(void* const* d_in, const int* in_sizes, int n_in,
                              void* d_out, int out_size) {
    const float* x    = (const float*)d_in[0];
    const int*   ei   = (const int*)d_in[1];
    const float* W0   = (const float*)d_in[2];
    const float* b0   = (const float*)d_in[3];
    const float* W1   = (const float*)d_in[4];
    const float* b1   = (const float*)d_in[5];
    const float* W2   = (const float*)d_in[6];
    const float* b2   = (const float*)d_in[7];
    const float* Wc   = (const float*)d_in[8];
    const float* bc   = (const float*)d_in[9];

    const int n = in_sizes[0] / DD;
    const int e = in_sizes[1] / 2;
    const int* src = ei;
    const int* dst = ei + e;

    float* out = (float*)d_out;
    float* logits = out;
    float* nf     = out + (size_t)n * CC;
    float* ep     = nf + (size_t)n * NF;

    float *buf_h, *buf_s, *dinv;
    int *cnt, *cursor, *rowptr, *csr_src;
    cudaGetSymbolAddress((void**)&buf_h, g_buf_h);
    cudaGetSymbolAddress((void**)&buf_s, g_buf_s);
    cudaGetSymbolAddress((void**)&dinv, g_dinv);
    cudaGetSymbolAddress((void**)&cnt, g_cnt);
    cudaGetSymbolAddress((void**)&cursor, g_cursor);
    cudaGetSymbolAddress((void**)&rowptr, g_rowptr);
    cudaGetSymbolAddress((void**)&csr_src, g_csr_src);

    const int TB = 256;
    k_zero2<<<(n + TB - 1) / TB, TB>>>(cnt, cursor, n);
    k_count<<<(e + TB - 1) / TB, TB>>>(dst, cnt, e);
    k_scan<<<1, 1024>>>(cnt, rowptr, n);
    k_dinv<<<(n + TB - 1) / TB, TB>>>(cnt, dinv, n);
    k_fill<<<(e + TB - 1) / TB, TB>>>(src, dst, rowptr, cursor, csr_src, e);

    dim3 gg((n + 127) / 128, TCN / 128);
    // layer 1: mma GEMM (D->H), aggregate+tanh -> nf cols [0,256)
    k_gemm_mma<<<gg, 256>>>(x, DD, W0, buf_h, n, DD);
    k_agg<<<n, HH>>>(buf_h, HH, nf, NF, rowptr, csr_src, dinv, b0);

    // layer 2: mma GEMM (H->H) reading h1 from nf (stride 513)
    k_gemm_mma<<<gg, 256>>>(nf, NF, W1, buf_h, n, HH);
    k_agg<<<n, HH>>>(buf_h, HH, nf + HH, NF, rowptr, csr_src, dinv, b1);

    // layer 3: project to scalar, aggregate scalars -> nf col 512
    k_dot_w2<<<(n * 32 + TB - 1) / TB, TB>>>(nf, W2, buf_s, n);
    k_agg_scalar<<<(n + TB - 1) / TB, TB>>>(buf_s, nf, rowptr, csr_src, dinv, b2, n);

    // classifier + edge pairs
    k_logits<<<(n * 32 + TB - 1) / TB, TB>>>(nf, Wc, bc, logits, n);
    k_edge_pairs<<<e, 256>>>(nf, src, dst, ep, e);
}

// round 9
// speedup vs baseline: 2.1122x; 1.3451x over previous
#include <cuda_runtime.h>
#include <cuda_bf16.h>
#include <math.h>
#include <stdint.h>

// Problem constants
#define NN 20000
#define EE 160000
#define DD 768
#define HH 256
#define CC 10
#define NF 513          // 2H+1
#define EPW 1026        // 2*(2H+1)
#define TCN 256         // GEMM N (fixed)

// -------- scratch (static device arrays are allowed) --------
__device__ float g_buf_h[NN * HH];
__device__ float g_buf_s[NN];
__device__ float g_dinv[NN];
__device__ int   g_cnt_dst[NN];
__device__ int   g_cnt_src[NN];
__device__ int   g_cur_dst[NN];
__device__ int   g_cur_src[NN];
__device__ int   g_rp_dst[NN + 1];
__device__ int   g_rp_src[NN + 1];
__device__ int   g_csr_srcnode[EE];   // by dst: src node id
__device__ int   g_csr_eid_dst[EE];   // by dst: edge id
__device__ int   g_csr_eid_src[EE];   // by src: edge id
__device__ __nv_bfloat16 g_xhi[NN * DD];
__device__ __nv_bfloat16 g_xlo[NN * DD];
__device__ __nv_bfloat16 g_h1hi[NN * HH];
__device__ __nv_bfloat16 g_h1lo[NN * HH];
__device__ __nv_bfloat16 g_bthi[HH * DD];   // transposed weight, max 256x768
__device__ __nv_bfloat16 g_btlo[HH * DD];

// ================= helpers =================
__device__ __forceinline__ uint32_t smem_u32(const void* p) {
    uint32_t a;
    asm("{ .reg .u64 t; cvta.to.shared.u64 t, %1; cvt.u32.u64 %0, t; }" : "=r"(a) : "l"(p));
    return a;
}
__device__ __forceinline__ void ldsm4(uint32_t* r, uint32_t addr) {
    asm volatile("ldmatrix.sync.aligned.m8n8.x4.shared.b16 {%0,%1,%2,%3}, [%4];"
                 : "=r"(r[0]), "=r"(r[1]), "=r"(r[2]), "=r"(r[3]) : "r"(addr));
}
__device__ __forceinline__ void mma_bf16(float* c, const uint32_t* a, const uint32_t* b) {
    asm volatile(
        "mma.sync.aligned.m16n8k16.row.col.f32.bf16.bf16.f32 "
        "{%0,%1,%2,%3}, {%4,%5,%6,%7}, {%8,%9}, {%0,%1,%2,%3};"
        : "+f"(c[0]), "+f"(c[1]), "+f"(c[2]), "+f"(c[3])
        : "r"(a[0]), "r"(a[1]), "r"(a[2]), "r"(a[3]), "r"(b[0]), "r"(b[1]));
}
__device__ __forceinline__ void cp16(uint32_t dst, const void* src, int sz) {
    asm volatile("cp.async.cg.shared.global [%0], [%1], 16, %2;"
                 :: "r"(dst), "l"(src), "r"(sz));
}
#define CP_COMMIT() asm volatile("cp.async.commit_group;" ::: "memory")
#define CP_WAIT(n)  asm volatile("cp.async.wait_group %0;" :: "n"(n) : "memory")

__device__ __forceinline__ float tanh_fast(float x) {
    float y; asm("tanh.approx.f32 %0, %1;" : "=f"(y) : "f"(x)); return y;
}
__device__ __forceinline__ void bf16_split(float v, __nv_bfloat16& hi, __nv_bfloat16& lo) {
    hi = __float2bfloat16(v);
    lo = __float2bfloat16(v - __bfloat162float(hi));
}

// ================= bf16 GEMM via mma.sync, cp.async double-buffered =================
// C[M x 256] = A[M x K] * Bt[256 x K]^T   (A,Bt pre-split bf16 hi/lo, row-major)
// BM=128, BN=128, BK=32; 256 thr = 8 warps (2m x 4n), warp tile 64x32.
#define BKK 32
#define SPAD 40                          // bf16 elems per smem row (80B, ldsm conflict-free)
#define MAT_BYTES (128 * SPAD * 2)       // 10240
#define STAGE_BYTES (4 * MAT_BYTES)      // Ah, Al, Bh, Bl = 40960
#define GEMM_SMEM (2 * STAGE_BYTES)      // 81920

__global__ void __launch_bounds__(256) k_gemm_bf16(
    const __nv_bfloat16* __restrict__ Ahi, const __nv_bfloat16* __restrict__ Alo,
    const __nv_bfloat16* __restrict__ Bthi, const __nv_bfloat16* __restrict__ Btlo,
    float* __restrict__ C, int M, int K)
{
    extern __shared__ char smem[];
    const uint32_t sbase = smem_u32(smem);
    const int tid = threadIdx.x;
    const int wid = tid >> 5, lane = tid & 31;
    const int row0 = blockIdx.x * 128;
    const int col0 = blockIdx.y * 128;
    const int wm = wid & 1, wn = wid >> 1;

    const int a_row = (lane & 7) + ((lane >> 3) & 1) * 8;
    const int a_col = ((lane >> 4) & 1) * 8;
    const int b_row = (lane & 7) + ((lane >> 4) & 1) * 8;
    const int b_col = ((lane >> 3) & 1) * 8;

    float acc[4][4][4] = {};
    const int nchunks = K / BKK;

    // ---- async load of one stage ----
    auto load_stage = [&](int buf, int c) {
        const int k0 = c * BKK;
        const uint32_t sA_h = sbase + buf * STAGE_BYTES;
        const uint32_t sA_l = sA_h + MAT_BYTES;
        const uint32_t sB_h = sA_l + MAT_BYTES;
        const uint32_t sB_l = sB_h + MAT_BYTES;
        #pragma unroll
        for (int t = tid; t < 512; t += 256) {          // A: 128 rows x 4 chunks
            int r = t >> 2, ch = t & 3;
            int gr = row0 + r;
            int ok = (gr < M);
            size_t off = (size_t)(ok ? gr : 0) * K + k0 + ch * 8;
            uint32_t d = (uint32_t)((r * SPAD + ch * 8) * 2);
            cp16(sA_h + d, Ahi + off, ok ? 16 : 0);
            cp16(sA_l + d, Alo + off, ok ? 16 : 0);
        }
        #pragma unroll
        for (int t = tid; t < 512; t += 256) {          // B: 128 n-rows x 4 chunks
            int n = t >> 2, ch = t & 3;
            size_t off = (size_t)(col0 + n) * K + k0 + ch * 8;
            uint32_t d = (uint32_t)((n * SPAD + ch * 8) * 2);
            cp16(sB_h + d, Bthi + off, 16);
            cp16(sB_l + d, Btlo + off, 16);
        }
    };

    auto compute_stage = [&](int buf) {
        const uint32_t sA_h = sbase + buf * STAGE_BYTES;
        const uint32_t sA_l = sA_h + MAT_BYTES;
        const uint32_t sB_h = sA_l + MAT_BYTES;
        const uint32_t sB_l = sB_h + MAT_BYTES;
        #pragma unroll
        for (int ks = 0; ks < 2; ++ks) {
            const int kc = ks * 16;
            uint32_t ah[4][4], al[4][4], bh[4][2], bl[4][2];
            #pragma unroll
            for (int mf = 0; mf < 4; ++mf) {
                uint32_t off = (uint32_t)((wm * 64 + mf * 16 + a_row) * SPAD + kc + a_col) * 2;
                ldsm4(ah[mf], sA_h + off);
            }
            #pragma unroll
            for (int np = 0; np < 2; ++np) {
                uint32_t off = (uint32_t)((wn * 32 + np * 16 + b_row) * SPAD + kc + b_col) * 2;
                uint32_t t[4];
                ldsm4(t, sB_h + off);
                bh[np * 2][0] = t[0]; bh[np * 2][1] = t[1];
                bh[np * 2 + 1][0] = t[2]; bh[np * 2 + 1][1] = t[3];
            }
            #pragma unroll
            for (int mf = 0; mf < 4; ++mf)
                #pragma unroll
                for (int nf = 0; nf < 4; ++nf)
                    mma_bf16(acc[mf][nf], ah[mf], bh[nf]);
            #pragma unroll
            for (int np = 0; np < 2; ++np) {
                uint32_t off = (uint32_t)((wn * 32 + np * 16 + b_row) * SPAD + kc + b_col) * 2;
                uint32_t t[4];
                ldsm4(t, sB_l + off);
                bl[np * 2][0] = t[0]; bl[np * 2][1] = t[1];
                bl[np * 2 + 1][0] = t[2]; bl[np * 2 + 1][1] = t[3];
            }
            #pragma unroll
            for (int mf = 0; mf < 4; ++mf)
                #pragma unroll
                for (int nf = 0; nf < 4; ++nf)
                    mma_bf16(acc[mf][nf], ah[mf], bl[nf]);
            #pragma unroll
            for (int mf = 0; mf < 4; ++mf) {
                uint32_t off = (uint32_t)((wm * 64 + mf * 16 + a_row) * SPAD + kc + a_col) * 2;
                ldsm4(al[mf], sA_l + off);
            }
            #pragma unroll
            for (int mf = 0; mf < 4; ++mf)
                #pragma unroll
                for (int nf = 0; nf < 4; ++nf)
                    mma_bf16(acc[mf][nf], al[mf], bh[nf]);
        }
    };

    load_stage(0, 0);
    CP_COMMIT();
    for (int c = 0; c < nchunks; ++c) {
        if (c + 1 < nchunks) {
            load_stage((c + 1) & 1, c + 1);
            CP_COMMIT();
            CP_WAIT(1);
        } else {
            CP_WAIT(0);
        }
        __syncthreads();
        compute_stage(c & 1);
        __syncthreads();
    }

    const int gq = lane >> 2, rq = lane & 3;
    #pragma unroll
    for (int mf = 0; mf < 4; ++mf) {
        int gr0 = row0 + wm * 64 + mf * 16 + gq;
        int gr1 = gr0 + 8;
        #pragma unroll
        for (int nf = 0; nf < 4; ++nf) {
            int gc = col0 + wn * 32 + nf * 8 + rq * 2;
            if (gr0 < M) {
                C[(size_t)gr0 * TCN + gc]     = acc[mf][nf][0];
                C[(size_t)gr0 * TCN + gc + 1] = acc[mf][nf][1];
            }
            if (gr1 < M) {
                C[(size_t)gr1 * TCN + gc]     = acc[mf][nf][2];
                C[(size_t)gr1 * TCN + gc + 1] = acc[mf][nf][3];
            }
        }
    }
}

// ================= conversion kernels =================
// elementwise fp32 -> bf16 hi/lo split, float4 vectorized (n must be mult of 4)
__global__ void k_cvt_split(const float* __restrict__ in,
                            __nv_bfloat16* __restrict__ hi, __nv_bfloat16* __restrict__ lo,
                            int n4) {
    int i = blockIdx.x * blockDim.x + threadIdx.x;
    if (i >= n4) return;
    float4 v = reinterpret_cast<const float4*>(in)[i];
    __nv_bfloat16 h0, h1, h2, h3, l0, l1, l2, l3;
    bf16_split(v.x, h0, l0); bf16_split(v.y, h1, l1);
    bf16_split(v.z, h2, l2); bf16_split(v.w, h3, l3);
    reinterpret_cast<__nv_bfloat162*>(hi)[i * 2]     = __nv_bfloat162(h0, h1);
    reinterpret_cast<__nv_bfloat162*>(hi)[i * 2 + 1] = __nv_bfloat162(h2, h3);
    reinterpret_cast<__nv_bfloat162*>(lo)[i * 2]     = __nv_bfloat162(l0, l1);
    reinterpret_cast<__nv_bfloat162*>(lo)[i * 2 + 1] = __nv_bfloat162(l2, l3);
}

// W [K][256] -> Bt [256][K] bf16 hi/lo (tiled transpose)
__global__ void k_cvt_w(const float* __restrict__ W,
                        __nv_bfloat16* __restrict__ bthi, __nv_bfloat16* __restrict__ btlo,
                        int K) {
    __shared__ float t[32][33];
    int kb = blockIdx.x * 32, nb = blockIdx.y * 32;
    int tx = threadIdx.x, ty = threadIdx.y;   // 32 x 8
    #pragma unroll
    for (int j = ty; j < 32; j += 8)
        t[j][tx] = W[(size_t)(kb + j) * TCN + nb + tx];
    __syncthreads();
    #pragma unroll
    for (int j = ty; j < 32; j += 8) {
        float v = t[tx][j];                   // W[kb+tx][nb+j]
        __nv_bfloat16 h, l;
        bf16_split(v, h, l);
        bthi[(size_t)(nb + j) * K + kb + tx] = h;
        btlo[(size_t)(nb + j) * K + kb + tx] = l;
    }
}

// ================= CSR build =================
__global__ void k_zero4(int* a, int* b, int* c, int* d, int n) {
    int i = blockIdx.x * blockDim.x + threadIdx.x;
    if (i < n) { a[i] = 0; b[i] = 0; c[i] = 0; d[i] = 0; }
}

__global__ void k_count2(const int* __restrict__ src, const int* __restrict__ dst,
                         int* cnt_src, int* cnt_dst, int e) {
    int i = blockIdx.x * blockDim.x + threadIdx.x;
    if (i < e) {
        atomicAdd(&cnt_dst[dst[i]], 1);
        atomicAdd(&cnt_src[src[i]], 1);
    }
}

__global__ void k_scan(const int* __restrict__ cnt, int* rowptr, int n) {
    __shared__ int wsum[32];
    __shared__ int s_carry;
    int lane = threadIdx.x & 31, wid = threadIdx.x >> 5;
    if (threadIdx.x == 0) { rowptr[0] = 0; s_carry = 0; }
    __syncthreads();
    for (int base = 0; base < n; base += 1024) {
        int i = base + threadIdx.x;
        int x = (i < n) ? cnt[i] : 0;
        #pragma unroll
        for (int off = 1; off < 32; off <<= 1) {
            int t = __shfl_up_sync(0xffffffffu, x, off);
            if (lane >= off) x += t;
        }
        if (lane == 31) wsum[wid] = x;
        __syncthreads();
        if (wid == 0) {
            int w = wsum[lane];
            #pragma unroll
            for (int off = 1; off < 32; off <<= 1) {
                int t = __shfl_up_sync(0xffffffffu, w, off);
                if (lane >= off) w += t;
            }
            wsum[lane] = w;
        }
        __syncthreads();
        int carry_now = s_carry;
        int excl_w = (wid > 0) ? wsum[wid - 1] : 0;
        if (i < n) rowptr[i + 1] = x + excl_w + carry_now;
        __syncthreads();
        if (threadIdx.x == 0) s_carry = carry_now + wsum[31];
        __syncthreads();
    }
}

__global__ void k_dinv(const int* __restrict__ cnt, float* dinv, int n) {
    int i = blockIdx.x * blockDim.x + threadIdx.x;
    if (i < n) dinv[i] = rsqrtf((float)(cnt[i] + 1));
}

__global__ void k_fill(const int* __restrict__ src, const int* __restrict__ dst,
                       const int* __restrict__ rp_dst, const int* __restrict__ rp_src,
                       int* cur_dst, int* cur_src,
                       int* csr_srcnode, int* csr_eid_dst, int* csr_eid_src, int e) {
    int i = blockIdx.x * blockDim.x + threadIdx.x;
    if (i < e) {
        int s = src[i], d = dst[i];
        int pd = rp_dst[d] + atomicAdd(&cur_dst[d], 1);
        csr_srcnode[pd] = s;
        csr_eid_dst[pd] = i;
        int ps = rp_src[s] + atomicAdd(&cur_src[s], 1);
        csr_eid_src[ps] = i;
    }
}

// ================= aggregation =================
// layer 1: agg+tanh -> nf cols [0,256) fp32 AND h1 bf16 hi/lo for GEMM2
__global__ void k_agg1(const float* __restrict__ h,
                       float* __restrict__ nf,
                       const int* __restrict__ rowptr, const int* __restrict__ csrc,
                       const float* __restrict__ dinv, const float* __restrict__ bias,
                       __nv_bfloat16* __restrict__ h1hi, __nv_bfloat16* __restrict__ h1lo) {
    int v = blockIdx.x;
    int col = threadIdx.x;
    float dv = dinv[v];
    float acc = h[(size_t)v * HH + col] * dv;
    int e1 = rowptr[v + 1];
    for (int e = rowptr[v]; e < e1; ++e) {
        int s = csrc[e];
        acc = fmaf(h[(size_t)s * HH + col], dinv[s], acc);
    }
    float r = tanh_fast(acc * dv + bias[col]);
    nf[(size_t)v * NF + col] = r;
    __nv_bfloat16 hi, lo;
    bf16_split(r, hi, lo);
    h1hi[(size_t)v * HH + col] = hi;
    h1lo[(size_t)v * HH + col] = lo;
}

// layer 2: agg+tanh -> nf cols [256,512) AND fused dot with W2 -> s[v]
__global__ void k_agg2(const float* __restrict__ h,
                       float* __restrict__ nf,
                       const int* __restrict__ rowptr, const int* __restrict__ csrc,
                       const float* __restrict__ dinv, const float* __restrict__ bias,
                       const float* __restrict__ W2, float* __restrict__ sv) {
    __shared__ float red[8];
    int v = blockIdx.x;
    int col = threadIdx.x;
    int lane = col & 31, wrp = col >> 5;
    float dv = dinv[v];
    float acc = h[(size_t)v * HH + col] * dv;
    int e1 = rowptr[v + 1];
    for (int e = rowptr[v]; e < e1; ++e) {
        int s = csrc[e];
        acc = fmaf(h[(size_t)s * HH + col], dinv[s], acc);
    }
    float r = tanh_fast(acc * dv + bias[col]);
    nf[(size_t)v * NF + HH + col] = r;
    // block-reduce r * W2[col]
    float p = r * W2[col];
    #pragma unroll
    for (int off = 16; off; off >>= 1) p += __shfl_xor_sync(0xffffffffu, p, off);
    if (lane == 0) red[wrp] = p;
    __syncthreads();
    if (col == 0) {
        float t = 0.f;
        #pragma unroll
        for (int w = 0; w < 8; ++w) t += red[w];
        sv[v] = t;
    }
}

__global__ void k_agg_scalar(const float* __restrict__ s, float* __restrict__ nf,
                             const int* __restrict__ rowptr, const int* __restrict__ csrc,
                             const float* __restrict__ dinv, const float* __restrict__ b2, int n) {
    int v = blockIdx.x * blockDim.x + threadIdx.x;
    if (v >= n) return;
    float dv = dinv[v];
    float acc = s[v] * dv;
    int e1 = rowptr[v + 1];
    for (int e = rowptr[v]; e < e1; ++e) {
        int src = csrc[e];
        acc = fmaf(s[src], dinv[src], acc);
    }
    nf[(size_t)v * NF + (NF - 1)] = tanh_fast(acc * dv + b2[0]);
}

__global__ void k_logits(const float* __restrict__ nf, const float* __restrict__ Wc,
                         const float* __restrict__ bc, float* __restrict__ out, int n) {
    int gwarp = (blockIdx.x * blockDim.x + threadIdx.x) >> 5;
    int lane = threadIdx.x & 31;
    if (gwarp >= n) return;
    const float* row = nf + (size_t)gwarp * NF;
    float acc[CC] = {};
    for (int j = lane; j < NF; j += 32) {
        float v = row[j];
        const float* w = Wc + (size_t)j * CC;
        #pragma unroll
        for (int c = 0; c < CC; ++c) acc[c] = fmaf(v, w[c], acc[c]);
    }
    #pragma unroll
    for (int c = 0; c < CC; ++c)
        #pragma unroll
        for (int off = 16; off; off >>= 1) acc[c] += __shfl_xor_sync(0xffffffffu, acc[c], off);
    if (lane == 0) {
        #pragma unroll
        for (int c = 0; c < CC; ++c) out[(size_t)gwarp * CC + c] = acc[c] + bc[c];
    }
}

// node-centric edge scatter: read each nf row once, write to all edge slots
__global__ void k_edge_scatter(const float* __restrict__ nf,
                               const int* __restrict__ rp_src, const int* __restrict__ eid_src,
                               const int* __restrict__ rp_dst, const int* __restrict__ eid_dst,
                               float* __restrict__ ep) {
    __shared__ float row[NF];
    int v = blockIdx.x;
    for (int j = threadIdx.x; j < NF; j += blockDim.x)
        row[j] = nf[(size_t)v * NF + j];
    __syncthreads();
    int s0 = rp_src[v], s1 = rp_src[v + 1];
    for (int e = s0; e < s1; ++e) {
        float* o = ep + (size_t)eid_src[e] * EPW;
        for (int j = threadIdx.x; j < NF; j += blockDim.x)
            __stcs(o + j, row[j]);
    }
    int d0 = rp_dst[v], d1 = rp_dst[v + 1];
    for (int e = d0; e < d1; ++e) {
        float* o = ep + (size_t)eid_dst[e] * EPW + NF;
        for (int j = threadIdx.x; j < NF; j += blockDim.x)
            __stcs(o + j, row[j]);
    }
}

// ================= launch =================
extern "C" void kernel_launch(void* const* d_in, const int* in_sizes, int n_in,
                              void* d_out, int out_size) {
    const float* x    = (const float*)d_in[0];
    const int*   ei   = (const int*)d_in[1];
    const float* W0   = (const float*)d_in[2];
    const float* b0   = (const float*)d_in[3];
    const float* W1   = (const float*)d_in[4];
    const float* b1   = (const float*)d_in[5];
    const float* W2   = (const float*)d_in[6];
    const float* b2   = (const float*)d_in[7];
    const float* Wc   = (const float*)d_in[8];
    const float* bc   = (const float*)d_in[9];

    const int n = in_sizes[0] / DD;
    const int e = in_sizes[1] / 2;
    const int* src = ei;
    const int* dst = ei + e;

    float* out = (float*)d_out;
    float* logits = out;
    float* nf     = out + (size_t)n * CC;
    float* ep     = nf + (size_t)n * NF;

    float *buf_h, *buf_s, *dinv;
    int *cnt_d, *cnt_s, *cur_d, *cur_s, *rp_d, *rp_s, *csrn, *eid_d, *eid_s;
    __nv_bfloat16 *xhi, *xlo, *h1hi, *h1lo, *bthi, *btlo;
    cudaGetSymbolAddress((void**)&buf_h, g_buf_h);
    cudaGetSymbolAddress((void**)&buf_s, g_buf_s);
    cudaGetSymbolAddress((void**)&dinv, g_dinv);
    cudaGetSymbolAddress((void**)&cnt_d, g_cnt_dst);
    cudaGetSymbolAddress((void**)&cnt_s, g_cnt_src);
    cudaGetSymbolAddress((void**)&cur_d, g_cur_dst);
    cudaGetSymbolAddress((void**)&cur_s, g_cur_src);
    cudaGetSymbolAddress((void**)&rp_d, g_rp_dst);
    cudaGetSymbolAddress((void**)&rp_s, g_rp_src);
    cudaGetSymbolAddress((void**)&csrn, g_csr_srcnode);
    cudaGetSymbolAddress((void**)&eid_d, g_csr_eid_dst);
    cudaGetSymbolAddress((void**)&eid_s, g_csr_eid_src);
    cudaGetSymbolAddress((void**)&xhi, g_xhi);
    cudaGetSymbolAddress((void**)&xlo, g_xlo);
    cudaGetSymbolAddress((void**)&h1hi, g_h1hi);
    cudaGetSymbolAddress((void**)&h1lo, g_h1lo);
    cudaGetSymbolAddress((void**)&bthi, g_bthi);
    cudaGetSymbolAddress((void**)&btlo, g_btlo);

    cudaFuncSetAttribute(k_gemm_bf16, cudaFuncAttributeMaxDynamicSharedMemorySize, GEMM_SMEM);

    const int TB = 256;
    dim3 gg((n + 127) / 128, TCN / 128);
    dim3 wb0(DD / 32, TCN / 32), wb1(HH / 32, TCN / 32);
    dim3 wt(32, 8);

    // -- launches ordered so GEMM1 is launch index 3 (ncu's capture slot) --
    k_zero4<<<(n + TB - 1) / TB, TB>>>(cnt_d, cnt_s, cur_d, cur_s, n);             // 0
    k_cvt_w<<<wb0, wt>>>(W0, bthi, btlo, DD);                                      // 1
    k_cvt_split<<<(n * DD / 4 + TB - 1) / TB, TB>>>(x, xhi, xlo, n * DD / 4);      // 2
    k_gemm_bf16<<<gg, 256, GEMM_SMEM>>>(xhi, xlo, bthi, btlo, buf_h, n, DD);       // 3
    k_count2<<<(e + TB - 1) / TB, TB>>>(src, dst, cnt_s, cnt_d, e);                // 4
    k_scan<<<1, 1024>>>(cnt_d, rp_d, n);                                           // 5
    k_scan<<<1, 1024>>>(cnt_s, rp_s, n);                                           // 6
    k_dinv<<<(n + TB - 1) / TB, TB>>>(cnt_d, dinv, n);                             // 7
    k_fill<<<(e + TB - 1) / TB, TB>>>(src, dst, rp_d, rp_s, cur_d, cur_s,
                                      csrn, eid_d, eid_s, e);                      // 8
    k_agg1<<<n, HH>>>(buf_h, nf, rp_d, csrn, dinv, b0, h1hi, h1lo);                // 9
    k_cvt_w<<<wb1, wt>>>(W1, bthi, btlo, HH);                                      // 10
    k_gemm_bf16<<<gg, 256, GEMM_SMEM>>>(h1hi, h1lo, bthi, btlo, buf_h, n, HH);     // 11
    k_agg2<<<n, HH>>>(buf_h, nf, rp_d, csrn, dinv, b1, W2, buf_s);                 // 12
    k_agg_scalar<<<(n + TB - 1) / TB, TB>>>(buf_s, nf, rp_d, csrn, dinv, b2, n);   // 13
    k_logits<<<(n * 32 + TB - 1) / TB, TB>>>(nf, Wc, bc, logits, n);               // 14
    k_edge_scatter<<<n, 256>>>(nf, rp_s, eid_s, rp_d, eid_d, ep);                  // 15
}